// round 4
// baseline (speedup 1.0000x reference)
#include <cuda_runtime.h>
#include <math.h>

#define L 4096
#define D 768
#define H 12
#define DK 64

typedef unsigned long long ull;

// ---- scratch (device globals: allocation-free per harness rules) ----
__device__ float g_Q[H * L * DK];     // head-major, pre-scaled by 1/8
__device__ float g_K[H * L * DK];     // head-major
__device__ float g_V[H * L * DK];     // head-major
__device__ float g_M[H * L];          // row max of scores
__device__ float g_Li[H * L];         // 1 / row sum of exp
__device__ float g_CTX[L * D];        // context, row-major [l][h*64+d]

// packed f32x2 FMA: acc.{lo,hi} += a.{lo,hi} * b.{lo,hi}
__device__ __forceinline__ void ffma2(ull& acc, ull a, ull b) {
    asm("fma.rn.f32x2 %0, %1, %2, %0;" : "+l"(acc) : "l"(a), "l"(b));
}
__device__ __forceinline__ float2 unpk(ull v) {
    float2 f;
    asm("mov.b64 {%0, %1}, %2;" : "=f"(f.x), "=f"(f.y) : "l"(v));
    return f;
}

// ============================================================================
// Generic tiled GEMM: C[m][n] = sum_d X[m][d] * W[n][d] + bias[n]
// 128x128 tile, BK=16, 256 threads, 8x8 micro-tile, packed f32x2 math.
// MODE 0/1/2: out = g_Q/g_K/g_V (head-major), MODE 0 scales by 1/8
// MODE 3:     X = g_CTX, out = Oout row-major (final projection)
// ============================================================================
template <int MODE>
__global__ __launch_bounds__(256) void gemm_kernel(const float* __restrict__ Xin,
                                                   const float* __restrict__ W,
                                                   const float* __restrict__ bias,
                                                   float* __restrict__ Oout) {
    __shared__ float As2[16][264];  // A^T duplicated: [k][2m]=[2m+1]=A[m]
    __shared__ float Bs[16][132];   // B^T plain: [k][n]
    const float* X = (MODE == 3) ? (const float*)g_CTX : Xin;

    const int m0 = blockIdx.y * 128;
    const int n0 = blockIdx.x * 128;
    const int t = threadIdx.x;
    const int tx = t & 15;   // col group (8 cols)
    const int ty = t >> 4;   // row group (8 rows)

    ull acc[8][4];
#pragma unroll
    for (int i = 0; i < 8; i++)
#pragma unroll
        for (int j = 0; j < 4; j++) acc[i][j] = 0ull;

    const int lr = t >> 2;          // 0..63
    const int lc = (t & 3) << 2;    // 0,4,8,12

    for (int k0 = 0; k0 < D; k0 += 16) {
#pragma unroll
        for (int it = 0; it < 2; it++) {
            const int r = lr + it * 64;
            float4 a = *(const float4*)&X[(size_t)(m0 + r) * D + k0 + lc];
            *(float2*)&As2[lc + 0][2 * r] = make_float2(a.x, a.x);
            *(float2*)&As2[lc + 1][2 * r] = make_float2(a.y, a.y);
            *(float2*)&As2[lc + 2][2 * r] = make_float2(a.z, a.z);
            *(float2*)&As2[lc + 3][2 * r] = make_float2(a.w, a.w);
            float4 b = *(const float4*)&W[(size_t)(n0 + r) * D + k0 + lc];
            Bs[lc + 0][r] = b.x; Bs[lc + 1][r] = b.y;
            Bs[lc + 2][r] = b.z; Bs[lc + 3][r] = b.w;
        }
        __syncthreads();
#pragma unroll
        for (int k = 0; k < 16; k++) {
            ulonglong2 a0 = *(const ulonglong2*)&As2[k][ty * 16];
            ulonglong2 a1 = *(const ulonglong2*)&As2[k][ty * 16 + 4];
            ulonglong2 a2 = *(const ulonglong2*)&As2[k][ty * 16 + 8];
            ulonglong2 a3 = *(const ulonglong2*)&As2[k][ty * 16 + 12];
            ulonglong2 b0 = *(const ulonglong2*)&Bs[k][tx * 8];
            ulonglong2 b1 = *(const ulonglong2*)&Bs[k][tx * 8 + 4];
            ull ad[8] = {a0.x, a0.y, a1.x, a1.y, a2.x, a2.y, a3.x, a3.y};
            ull bd[4] = {b0.x, b0.y, b1.x, b1.y};
#pragma unroll
            for (int i = 0; i < 8; i++)
#pragma unroll
                for (int j = 0; j < 4; j++) ffma2(acc[i][j], ad[i], bd[j]);
        }
        __syncthreads();
    }

#pragma unroll
    for (int i = 0; i < 8; i++) {
        const int row = m0 + ty * 8 + i;
#pragma unroll
        for (int jp = 0; jp < 4; jp++) {
            float2 c = unpk(acc[i][jp]);
            float cv[2] = {c.x, c.y};
#pragma unroll
            for (int e = 0; e < 2; e++) {
                const int col = n0 + tx * 8 + 2 * jp + e;
                float v = cv[e] + bias[col];
                if (MODE == 0) v *= 0.125f;  // fold in 1/sqrt(d_k)
                if (MODE == 0) {
                    g_Q[((size_t)((col >> 6) * L) + row) * DK + (col & 63)] = v;
                } else if (MODE == 1) {
                    g_K[((size_t)((col >> 6) * L) + row) * DK + (col & 63)] = v;
                } else if (MODE == 2) {
                    g_V[((size_t)((col >> 6) * L) + row) * DK + (col & 63)] = v;
                } else {
                    Oout[(size_t)row * D + col] = v;
                }
            }
        }
    }
}

// ============================================================================
// Fused scores + softmax stats (packed f32x2), Q resident in shared.
// Block owns a 128-row strip of one head. Q strip staged ONCE (duplicated
// pairs, dynamic smem); per 128-col k-tile only K is staged (2 syncs/tile).
// S = Q.K^T (Q pre-scaled), mask, raw scores -> attn, per-row online stats.
// ============================================================================
#define QS2_ELEMS (DK * 264)      // duplicated Q: [d][2q], 264-float rows
#define KS_ELEMS  (DK * 132)      // plain K^T: [d][k], 132-float rows
#define SCORES_SMEM ((QS2_ELEMS + KS_ELEMS) * (int)sizeof(float))

__global__ __launch_bounds__(256) void scores_stats_kernel(const int* __restrict__ mask,
                                                           float* __restrict__ attn) {
    extern __shared__ float dyn[];
    float* Qs2 = dyn;                 // [DK][264]
    float* Ks = dyn + QS2_ELEMS;      // [DK][132]
    __shared__ float Sm[128][17];
    __shared__ float Sl[128][17];

    const int h = blockIdx.y;
    const int q0 = blockIdx.x * 128;
    const int t = threadIdx.x;
    const int tx = t & 15;
    const int ty = t >> 4;

    // stage Q strip once: 128 rows x 64 d, duplicated pairs
    for (int idx = t; idx < 128 * 16; idx += 256) {
        const int row = idx >> 4;
        const int dc = (idx & 15) * 4;
        float4 q = *(const float4*)&g_Q[((size_t)(h * L + q0 + row)) * DK + dc];
        *(float2*)&Qs2[(dc + 0) * 264 + 2 * row] = make_float2(q.x, q.x);
        *(float2*)&Qs2[(dc + 1) * 264 + 2 * row] = make_float2(q.y, q.y);
        *(float2*)&Qs2[(dc + 2) * 264 + 2 * row] = make_float2(q.z, q.z);
        *(float2*)&Qs2[(dc + 3) * 264 + 2 * row] = make_float2(q.w, q.w);
    }

    float rm[8], rl[8];
#pragma unroll
    for (int i = 0; i < 8; i++) { rm[i] = -3.0e38f; rl[i] = 0.f; }

    for (int k0 = 0; k0 < L; k0 += 128) {
        // stage K tile: 128 k-rows x 64 d, transposed to [d][k]
        for (int idx = t; idx < 128 * 16; idx += 256) {
            const int kr = idx >> 4;
            const int dc = (idx & 15) * 4;
            float4 kv = *(const float4*)&g_K[((size_t)(h * L + k0 + kr)) * DK + dc];
            Ks[(dc + 0) * 132 + kr] = kv.x;
            Ks[(dc + 1) * 132 + kr] = kv.y;
            Ks[(dc + 2) * 132 + kr] = kv.z;
            Ks[(dc + 3) * 132 + kr] = kv.w;
        }
        __syncthreads();  // K (and, first iter, Q) visible

        ull acc[8][4];
#pragma unroll
        for (int i = 0; i < 8; i++)
#pragma unroll
            for (int j = 0; j < 4; j++) acc[i][j] = 0ull;

#pragma unroll 16
        for (int d = 0; d < DK; d++) {
            const float* qrow = &Qs2[d * 264 + ty * 16];
            const float* krow = &Ks[d * 132 + tx * 8];
            ulonglong2 a0 = *(const ulonglong2*)&qrow[0];
            ulonglong2 a1 = *(const ulonglong2*)&qrow[4];
            ulonglong2 a2 = *(const ulonglong2*)&qrow[8];
            ulonglong2 a3 = *(const ulonglong2*)&qrow[12];
            ulonglong2 b0 = *(const ulonglong2*)&krow[0];
            ulonglong2 b1 = *(const ulonglong2*)&krow[4];
            ull ad[8] = {a0.x, a0.y, a1.x, a1.y, a2.x, a2.y, a3.x, a3.y};
            ull bd[4] = {b0.x, b0.y, b1.x, b1.y};
#pragma unroll
            for (int i = 0; i < 8; i++)
#pragma unroll
                for (int j = 0; j < 4; j++) ffma2(acc[i][j], ad[i], bd[j]);
        }

        // mask + store raw scores + branch-free online stats merge
#pragma unroll
        for (int i = 0; i < 8; i++) {
            const int q = q0 + ty * 8 + i;
            const int kk = k0 + tx * 8;
            int4 m0v = *(const int4*)&mask[(size_t)q * L + kk];
            int4 m1v = *(const int4*)&mask[(size_t)q * L + kk + 4];
            float2 c0 = unpk(acc[i][0]);
            float2 c1 = unpk(acc[i][1]);
            float2 c2 = unpk(acc[i][2]);
            float2 c3 = unpk(acc[i][3]);
            float v[8];
            v[0] = m0v.x ? c0.x : -1e9f;
            v[1] = m0v.y ? c0.y : -1e9f;
            v[2] = m0v.z ? c1.x : -1e9f;
            v[3] = m0v.w ? c1.y : -1e9f;
            v[4] = m1v.x ? c2.x : -1e9f;
            v[5] = m1v.y ? c2.y : -1e9f;
            v[6] = m1v.z ? c3.x : -1e9f;
            v[7] = m1v.w ? c3.y : -1e9f;

            const size_t o = ((size_t)(h * L + q)) * L + kk;
            *(float4*)&attn[o]     = make_float4(v[0], v[1], v[2], v[3]);
            *(float4*)&attn[o + 4] = make_float4(v[4], v[5], v[6], v[7]);

            float tmax = v[0];
#pragma unroll
            for (int j = 1; j < 8; j++) tmax = fmaxf(tmax, v[j]);
            const float nm = fmaxf(rm[i], tmax);
            float s = rl[i] * __expf(rm[i] - nm);
#pragma unroll
            for (int j = 0; j < 8; j++) s += __expf(v[j] - nm);
            rm[i] = nm;
            rl[i] = s;
        }
        __syncthreads();  // before next tile overwrites Ks
    }

    // cross-thread reduction: 16 tx-partials per row
#pragma unroll
    for (int i = 0; i < 8; i++) {
        Sm[ty * 8 + i][tx] = rm[i];
        Sl[ty * 8 + i][tx] = rl[i];
    }
    __syncthreads();
    if (t < 128) {
        float m = Sm[t][0];
#pragma unroll
        for (int j = 1; j < 16; j++) m = fmaxf(m, Sm[t][j]);
        float l = 0.f;
#pragma unroll
        for (int j = 0; j < 16; j++) l += Sl[t][j] * __expf(Sm[t][j] - m);
        g_M[h * L + q0 + t] = m;
        g_Li[h * L + q0 + t] = 1.f / l;
    }
}

// ============================================================================
// attn finalize + ctx = P @ V (packed f32x2).
// P staged transposed Pt[k][q] (natural row-pairs), V staged duplicated.
// ============================================================================
__global__ __launch_bounds__(256) void attnv_kernel(float* __restrict__ attn) {
    __shared__ float Pt[32][132];   // transposed P: [k][q]
    __shared__ float Vs2[32][136];  // duplicated V: [k][2d]=[2d+1]=V[k][d]
    __shared__ float Ms[128], Lis[128];

    const int h = blockIdx.y;
    const int q0 = blockIdx.x * 128;
    const int t = threadIdx.x;
    const int tx = t & 15;   // col group: 4 col-pairs
    const int ty = t >> 4;   // row group: 8 rows (4 row-pairs)

    if (t < 128) {
        Ms[t] = g_M[h * L + q0 + t];
        Lis[t] = g_Li[h * L + q0 + t];
    }
    __syncthreads();

    ull acc[4][4];  // [row-pair][col]
#pragma unroll
    for (int i = 0; i < 4; i++)
#pragma unroll
        for (int j = 0; j < 4; j++) acc[i][j] = 0ull;

    const int sr = t >> 3;          // 0..31 (q row within pass)
    const int sc = (t & 7) << 2;    // 0,4,...,28 (k col)
    const int vr = t >> 4;          // 0..15
    const int vc = (t & 15) << 2;   // 0..60

    for (int k0 = 0; k0 < L; k0 += 32) {
        // phase 1: scores -> p (overwrite attn), stage transposed into Pt
#pragma unroll
        for (int pass = 0; pass < 4; pass++) {
            const int r = sr + pass * 32;
            const size_t idx = ((size_t)(h * L + q0 + r)) * L + k0 + sc;
            float4 s = *(const float4*)&attn[idx];
            const float m = Ms[r];
            const float li = Lis[r];
            float4 p;
            p.x = __expf(s.x - m) * li;
            p.y = __expf(s.y - m) * li;
            p.z = __expf(s.z - m) * li;
            p.w = __expf(s.w - m) * li;
            *(float4*)&attn[idx] = p;
            Pt[sc + 0][r] = p.x;
            Pt[sc + 1][r] = p.y;
            Pt[sc + 2][r] = p.z;
            Pt[sc + 3][r] = p.w;
        }
        // load V tile, duplicated pairs
#pragma unroll
        for (int pass = 0; pass < 2; pass++) {
            const int r = vr + pass * 16;
            float4 v = *(const float4*)&g_V[((size_t)(h * L) + k0 + r) * DK + vc];
            *(float2*)&Vs2[r][2 * (vc + 0)] = make_float2(v.x, v.x);
            *(float2*)&Vs2[r][2 * (vc + 1)] = make_float2(v.y, v.y);
            *(float2*)&Vs2[r][2 * (vc + 2)] = make_float2(v.z, v.z);
            *(float2*)&Vs2[r][2 * (vc + 3)] = make_float2(v.w, v.w);
        }
        __syncthreads();
        // ctx += P @ V
#pragma unroll
        for (int k = 0; k < 32; k++) {
            ulonglong2 p01 = *(const ulonglong2*)&Pt[k][ty * 8];
            ulonglong2 p23 = *(const ulonglong2*)&Pt[k][ty * 8 + 4];
            ulonglong2 v01 = *(const ulonglong2*)&Vs2[k][tx * 8];
            ulonglong2 v23 = *(const ulonglong2*)&Vs2[k][tx * 8 + 4];
            ull pd[4] = {p01.x, p01.y, p23.x, p23.y};
            ull vd[4] = {v01.x, v01.y, v23.x, v23.y};
#pragma unroll
            for (int i = 0; i < 4; i++)
#pragma unroll
                for (int j = 0; j < 4; j++) ffma2(acc[i][j], pd[i], vd[j]);
        }
        __syncthreads();
    }

    // write ctx row-major [l][h*64+d]; acc[i][j] = (ctx[2i][j], ctx[2i+1][j])
#pragma unroll
    for (int i = 0; i < 4; i++) {
        float2 c0 = unpk(acc[i][0]);
        float2 c1 = unpk(acc[i][1]);
        float2 c2 = unpk(acc[i][2]);
        float2 c3 = unpk(acc[i][3]);
        const int row_lo = q0 + ty * 8 + 2 * i;
        *(float4*)&g_CTX[(size_t)row_lo * D + h * DK + tx * 4] =
            make_float4(c0.x, c1.x, c2.x, c3.x);
        *(float4*)&g_CTX[(size_t)(row_lo + 1) * D + h * DK + tx * 4] =
            make_float4(c0.y, c1.y, c2.y, c3.y);
    }
}

// ============================================================================
extern "C" void kernel_launch(void* const* d_in, const int* in_sizes, int n_in,
                              void* d_out, int out_size) {
    const float* query = (const float*)d_in[0];
    const float* key_  = (const float*)d_in[1];
    const float* value = (const float*)d_in[2];
    const int*   mask  = (const int*)d_in[3];
    const float* Wq = (const float*)d_in[4];
    const float* bq = (const float*)d_in[5];
    const float* Wk = (const float*)d_in[6];
    const float* bk = (const float*)d_in[7];
    const float* Wv = (const float*)d_in[8];
    const float* bv = (const float*)d_in[9];
    const float* Wo = (const float*)d_in[10];
    const float* bo = (const float*)d_in[11];

    float* out = (float*)d_out;                    // [L, D]
    float* attn = out + (size_t)L * D;             // [H, L, L]

    cudaFuncSetAttribute(scores_stats_kernel,
                         cudaFuncAttributeMaxDynamicSharedMemorySize, SCORES_SMEM);

    dim3 gProj(D / 128, L / 128);
    gemm_kernel<0><<<gProj, 256>>>(query, Wq, bq, nullptr);
    gemm_kernel<1><<<gProj, 256>>>(key_, Wk, bk, nullptr);
    gemm_kernel<2><<<gProj, 256>>>(value, Wv, bv, nullptr);

    scores_stats_kernel<<<dim3(L / 128, H), 256, SCORES_SMEM>>>(mask, attn);
    attnv_kernel<<<dim3(L / 128, H), 256>>>(attn);

    gemm_kernel<3><<<gProj, 256>>>(nullptr, Wo, bo, out);
}

// round 5
// speedup vs baseline: 1.1172x; 1.1172x over previous
#include <cuda_runtime.h>
#include <math.h>

#define L 4096
#define D 768
#define H 12
#define DK 64

typedef unsigned long long ull;

// ---- scratch (device globals: allocation-free per harness rules) ----
__device__ float g_Q[H * L * DK];     // head-major, pre-scaled by 1/8
__device__ float g_K[H * L * DK];     // head-major
__device__ float g_V[H * L * DK];     // head-major
__device__ float g_M[H * L];          // row max of scores
__device__ float g_Li[H * L];         // 1 / row sum of exp
__device__ float g_CTX[L * D];        // context, row-major [l][h*64+d]

// packed f32x2 FMA: acc.{lo,hi} += a.{lo,hi} * b.{lo,hi}
__device__ __forceinline__ void ffma2(ull& acc, ull a, ull b) {
    asm("fma.rn.f32x2 %0, %1, %2, %0;" : "+l"(acc) : "l"(a), "l"(b));
}
__device__ __forceinline__ float2 unpk(ull v) {
    float2 f;
    asm("mov.b64 {%0, %1}, %2;" : "=f"(f.x), "=f"(f.y) : "l"(v));
    return f;
}
// duplicate one float into both halves of a 64-bit pair (1 MOV)
__device__ __forceinline__ ull dup2(float x) {
    ull r;
    asm("mov.b64 %0, {%1, %1};" : "=l"(r) : "f"(x));
    return r;
}

// ============================================================================
// Generic tiled GEMM: C[m][n] = sum_d X[m][d] * W[n][d] + bias[n]
// 128x128 tile, BK=16, 256 threads, 8x8 micro-tile, packed f32x2 math.
// A staged PLAIN (dup in registers), B staged plain (natural pairs).
// MODE 0/1/2: out = g_Q/g_K/g_V (head-major), MODE 0 scales by 1/8
// MODE 3:     X = g_CTX, out = Oout row-major (final projection)
// ============================================================================
template <int MODE>
__global__ __launch_bounds__(256, 2) void gemm_kernel(const float* __restrict__ Xin,
                                                      const float* __restrict__ W,
                                                      const float* __restrict__ bias,
                                                      float* __restrict__ Oout) {
    __shared__ float As[16][132];  // A^T plain: [k][m]
    __shared__ float Bs[16][132];  // B^T plain: [k][n]
    const float* X = (MODE == 3) ? (const float*)g_CTX : Xin;

    const int m0 = blockIdx.y * 128;
    const int n0 = blockIdx.x * 128;
    const int t = threadIdx.x;
    const int tx = t & 15;   // col group (8 cols)
    const int ty = t >> 4;   // row group (8 rows)

    ull acc[8][4];
#pragma unroll
    for (int i = 0; i < 8; i++)
#pragma unroll
        for (int j = 0; j < 4; j++) acc[i][j] = 0ull;

    const int lr = t >> 2;          // 0..63
    const int lc = (t & 3) << 2;    // 0,4,8,12

    for (int k0 = 0; k0 < D; k0 += 16) {
#pragma unroll
        for (int it = 0; it < 2; it++) {
            const int r = lr + it * 64;
            float4 a = *(const float4*)&X[(size_t)(m0 + r) * D + k0 + lc];
            As[lc + 0][r] = a.x; As[lc + 1][r] = a.y;
            As[lc + 2][r] = a.z; As[lc + 3][r] = a.w;
            float4 b = *(const float4*)&W[(size_t)(n0 + r) * D + k0 + lc];
            Bs[lc + 0][r] = b.x; Bs[lc + 1][r] = b.y;
            Bs[lc + 2][r] = b.z; Bs[lc + 3][r] = b.w;
        }
        __syncthreads();
#pragma unroll
        for (int k = 0; k < 16; k++) {
            float4 a0 = *(const float4*)&As[k][ty * 8];
            float4 a1 = *(const float4*)&As[k][ty * 8 + 4];
            ulonglong2 b0 = *(const ulonglong2*)&Bs[k][tx * 8];
            ulonglong2 b1 = *(const ulonglong2*)&Bs[k][tx * 8 + 4];
            ull ad[8] = {dup2(a0.x), dup2(a0.y), dup2(a0.z), dup2(a0.w),
                         dup2(a1.x), dup2(a1.y), dup2(a1.z), dup2(a1.w)};
            ull bd[4] = {b0.x, b0.y, b1.x, b1.y};
#pragma unroll
            for (int i = 0; i < 8; i++)
#pragma unroll
                for (int j = 0; j < 4; j++) ffma2(acc[i][j], ad[i], bd[j]);
        }
        __syncthreads();
    }

#pragma unroll
    for (int i = 0; i < 8; i++) {
        const int row = m0 + ty * 8 + i;
#pragma unroll
        for (int jp = 0; jp < 4; jp++) {
            float2 c = unpk(acc[i][jp]);
            float cv[2] = {c.x, c.y};
#pragma unroll
            for (int e = 0; e < 2; e++) {
                const int col = n0 + tx * 8 + 2 * jp + e;
                float v = cv[e] + bias[col];
                if (MODE == 0) v *= 0.125f;  // fold in 1/sqrt(d_k)
                if (MODE == 0) {
                    g_Q[((size_t)((col >> 6) * L) + row) * DK + (col & 63)] = v;
                } else if (MODE == 1) {
                    g_K[((size_t)((col >> 6) * L) + row) * DK + (col & 63)] = v;
                } else if (MODE == 2) {
                    g_V[((size_t)((col >> 6) * L) + row) * DK + (col & 63)] = v;
                } else {
                    Oout[(size_t)row * D + col] = v;
                }
            }
        }
    }
}

// ============================================================================
// Fused scores + softmax stats (packed f32x2), Q resident in shared (plain).
// Block owns a 128-row strip of one head. Q staged once; per 128-col k-tile
// only K staged. Register duplication keeps LDS at 4x LDS.128 per 32 FFMA2.
// ============================================================================
#define QS_ELEMS (DK * 132)
#define KS_ELEMS (DK * 132)
#define SCORES_SMEM ((QS_ELEMS + KS_ELEMS) * (int)sizeof(float))

__global__ __launch_bounds__(256, 2) void scores_stats_kernel(const int* __restrict__ mask,
                                                              float* __restrict__ attn) {
    extern __shared__ float dyn[];
    float* Qs = dyn;                 // [DK][132] plain [d][q]
    float* Ks = dyn + QS_ELEMS;      // [DK][132] plain [d][k]
    __shared__ float Sm[128][17];
    __shared__ float Sl[128][17];

    const int h = blockIdx.y;
    const int q0 = blockIdx.x * 128;
    const int t = threadIdx.x;
    const int tx = t & 15;
    const int ty = t >> 4;

    // stage Q strip once: 128 rows x 64 d, transposed to [d][q]
    for (int idx = t; idx < 128 * 16; idx += 256) {
        const int row = idx >> 4;
        const int dc = (idx & 15) * 4;
        float4 q = *(const float4*)&g_Q[((size_t)(h * L + q0 + row)) * DK + dc];
        Qs[(dc + 0) * 132 + row] = q.x;
        Qs[(dc + 1) * 132 + row] = q.y;
        Qs[(dc + 2) * 132 + row] = q.z;
        Qs[(dc + 3) * 132 + row] = q.w;
    }

    float rm[8], rl[8];
#pragma unroll
    for (int i = 0; i < 8; i++) { rm[i] = -3.0e38f; rl[i] = 0.f; }

    for (int k0 = 0; k0 < L; k0 += 128) {
        // stage K tile: 128 k-rows x 64 d, transposed to [d][k]
        for (int idx = t; idx < 128 * 16; idx += 256) {
            const int kr = idx >> 4;
            const int dc = (idx & 15) * 4;
            float4 kv = *(const float4*)&g_K[((size_t)(h * L + k0 + kr)) * DK + dc];
            Ks[(dc + 0) * 132 + kr] = kv.x;
            Ks[(dc + 1) * 132 + kr] = kv.y;
            Ks[(dc + 2) * 132 + kr] = kv.z;
            Ks[(dc + 3) * 132 + kr] = kv.w;
        }
        __syncthreads();

        ull acc[8][4];
#pragma unroll
        for (int i = 0; i < 8; i++)
#pragma unroll
            for (int j = 0; j < 4; j++) acc[i][j] = 0ull;

#pragma unroll 8
        for (int d = 0; d < DK; d++) {
            float4 a0 = *(const float4*)&Qs[d * 132 + ty * 8];
            float4 a1 = *(const float4*)&Qs[d * 132 + ty * 8 + 4];
            ulonglong2 b0 = *(const ulonglong2*)&Ks[d * 132 + tx * 8];
            ulonglong2 b1 = *(const ulonglong2*)&Ks[d * 132 + tx * 8 + 4];
            ull ad[8] = {dup2(a0.x), dup2(a0.y), dup2(a0.z), dup2(a0.w),
                         dup2(a1.x), dup2(a1.y), dup2(a1.z), dup2(a1.w)};
            ull bd[4] = {b0.x, b0.y, b1.x, b1.y};
#pragma unroll
            for (int i = 0; i < 8; i++)
#pragma unroll
                for (int j = 0; j < 4; j++) ffma2(acc[i][j], ad[i], bd[j]);
        }

        // mask + store raw scores + branch-free online stats merge
#pragma unroll
        for (int i = 0; i < 8; i++) {
            const int q = q0 + ty * 8 + i;
            const int kk = k0 + tx * 8;
            int4 m0v = *(const int4*)&mask[(size_t)q * L + kk];
            int4 m1v = *(const int4*)&mask[(size_t)q * L + kk + 4];
            float2 c0 = unpk(acc[i][0]);
            float2 c1 = unpk(acc[i][1]);
            float2 c2 = unpk(acc[i][2]);
            float2 c3 = unpk(acc[i][3]);
            float v[8];
            v[0] = m0v.x ? c0.x : -1e9f;
            v[1] = m0v.y ? c0.y : -1e9f;
            v[2] = m0v.z ? c1.x : -1e9f;
            v[3] = m0v.w ? c1.y : -1e9f;
            v[4] = m1v.x ? c2.x : -1e9f;
            v[5] = m1v.y ? c2.y : -1e9f;
            v[6] = m1v.z ? c3.x : -1e9f;
            v[7] = m1v.w ? c3.y : -1e9f;

            const size_t o = ((size_t)(h * L + q)) * L + kk;
            *(float4*)&attn[o]     = make_float4(v[0], v[1], v[2], v[3]);
            *(float4*)&attn[o + 4] = make_float4(v[4], v[5], v[6], v[7]);

            float tmax = v[0];
#pragma unroll
            for (int j = 1; j < 8; j++) tmax = fmaxf(tmax, v[j]);
            const float nm = fmaxf(rm[i], tmax);
            float s = rl[i] * __expf(rm[i] - nm);
#pragma unroll
            for (int j = 0; j < 8; j++) s += __expf(v[j] - nm);
            rm[i] = nm;
            rl[i] = s;
        }
        __syncthreads();  // before next tile overwrites Ks
    }

    // cross-thread reduction: 16 tx-partials per row
#pragma unroll
    for (int i = 0; i < 8; i++) {
        Sm[ty * 8 + i][tx] = rm[i];
        Sl[ty * 8 + i][tx] = rl[i];
    }
    __syncthreads();
    if (t < 128) {
        float m = Sm[t][0];
#pragma unroll
        for (int j = 1; j < 16; j++) m = fmaxf(m, Sm[t][j]);
        float l = 0.f;
#pragma unroll
        for (int j = 0; j < 16; j++) l += Sl[t][j] * __expf(Sm[t][j] - m);
        g_M[h * L + q0 + t] = m;
        g_Li[h * L + q0 + t] = 1.f / l;
    }
}

// ============================================================================
// attn finalize + ctx = P @ V (packed f32x2, register-dup V).
// Block: one head, 256 query rows x full DK=64. 8x8 micro-tile per thread.
// Streams 32-wide k-tiles: raw scores -> p (overwrite attn), Pt transposed
// in smem (natural row pairs), V plain (dup in regs).
// ============================================================================
__global__ __launch_bounds__(256, 2) void attnv_kernel(float* __restrict__ attn) {
    __shared__ float Pt[32][264];   // transposed P: [k][q], 256 q + pad
    __shared__ float Vs[32][68];    // plain V: [k][d]
    __shared__ float Ms[256], Lis[256];

    const int h = blockIdx.y;
    const int q0 = blockIdx.x * 256;
    const int t = threadIdx.x;
    const int tx = t & 7;    // col group: 8 cols
    const int ty = t >> 3;   // row group: 8 rows (4 row-pairs), 0..31

    Ms[t] = g_M[h * L + q0 + t];
    Lis[t] = g_Li[h * L + q0 + t];
    __syncthreads();

    ull acc[4][8];  // [row-pair][col]
#pragma unroll
    for (int i = 0; i < 4; i++)
#pragma unroll
        for (int j = 0; j < 8; j++) acc[i][j] = 0ull;

    const int sr = t >> 3;          // 0..31 (q row within pass)
    const int sc = (t & 7) << 2;    // 0,4,...,28 (k col)
    const int vr = t >> 3;          // 0..31
    const int vc = (t & 7) << 3;    // 0..56

    for (int k0 = 0; k0 < L; k0 += 32) {
        // phase 1: scores -> p (overwrite attn), stage transposed into Pt
#pragma unroll
        for (int pass = 0; pass < 8; pass++) {
            const int r = sr + pass * 32;
            const size_t idx = ((size_t)(h * L + q0 + r)) * L + k0 + sc;
            float4 s = *(const float4*)&attn[idx];
            const float m = Ms[r];
            const float li = Lis[r];
            float4 p;
            p.x = __expf(s.x - m) * li;
            p.y = __expf(s.y - m) * li;
            p.z = __expf(s.z - m) * li;
            p.w = __expf(s.w - m) * li;
            *(float4*)&attn[idx] = p;
            Pt[sc + 0][r] = p.x;
            Pt[sc + 1][r] = p.y;
            Pt[sc + 2][r] = p.z;
            Pt[sc + 3][r] = p.w;
        }
        // load V tile (32 rows x 64 d), plain
        {
            float4 v0 = *(const float4*)&g_V[((size_t)(h * L) + k0 + vr) * DK + vc];
            float4 v1 = *(const float4*)&g_V[((size_t)(h * L) + k0 + vr) * DK + vc + 4];
            *(float4*)&Vs[vr][vc] = v0;
            *(float4*)&Vs[vr][vc + 4] = v1;
        }
        __syncthreads();
        // ctx += P @ V
#pragma unroll 8
        for (int k = 0; k < 32; k++) {
            ulonglong2 p01 = *(const ulonglong2*)&Pt[k][ty * 8];
            ulonglong2 p23 = *(const ulonglong2*)&Pt[k][ty * 8 + 4];
            float4 v0 = *(const float4*)&Vs[k][tx * 8];
            float4 v1 = *(const float4*)&Vs[k][tx * 8 + 4];
            ull pd[4] = {p01.x, p01.y, p23.x, p23.y};
            ull vd[8] = {dup2(v0.x), dup2(v0.y), dup2(v0.z), dup2(v0.w),
                         dup2(v1.x), dup2(v1.y), dup2(v1.z), dup2(v1.w)};
#pragma unroll
            for (int i = 0; i < 4; i++)
#pragma unroll
                for (int j = 0; j < 8; j++) ffma2(acc[i][j], pd[i], vd[j]);
        }
        __syncthreads();
    }

    // write ctx row-major [l][h*64+d]; acc[i][j] = (ctx[2i][j], ctx[2i+1][j])
#pragma unroll
    for (int i = 0; i < 4; i++) {
        float2 c[8];
#pragma unroll
        for (int j = 0; j < 8; j++) c[j] = unpk(acc[i][j]);
        const int row_lo = q0 + ty * 8 + 2 * i;
        float* dst0 = &g_CTX[(size_t)row_lo * D + h * DK + tx * 8];
        float* dst1 = &g_CTX[(size_t)(row_lo + 1) * D + h * DK + tx * 8];
        *(float4*)&dst0[0] = make_float4(c[0].x, c[1].x, c[2].x, c[3].x);
        *(float4*)&dst0[4] = make_float4(c[4].x, c[5].x, c[6].x, c[7].x);
        *(float4*)&dst1[0] = make_float4(c[0].y, c[1].y, c[2].y, c[3].y);
        *(float4*)&dst1[4] = make_float4(c[4].y, c[5].y, c[6].y, c[7].y);
    }
}

// ============================================================================
extern "C" void kernel_launch(void* const* d_in, const int* in_sizes, int n_in,
                              void* d_out, int out_size) {
    const float* query = (const float*)d_in[0];
    const float* key_  = (const float*)d_in[1];
    const float* value = (const float*)d_in[2];
    const int*   mask  = (const int*)d_in[3];
    const float* Wq = (const float*)d_in[4];
    const float* bq = (const float*)d_in[5];
    const float* Wk = (const float*)d_in[6];
    const float* bk = (const float*)d_in[7];
    const float* Wv = (const float*)d_in[8];
    const float* bv = (const float*)d_in[9];
    const float* Wo = (const float*)d_in[10];
    const float* bo = (const float*)d_in[11];

    float* out = (float*)d_out;                    // [L, D]
    float* attn = out + (size_t)L * D;             // [H, L, L]

    cudaFuncSetAttribute(scores_stats_kernel,
                         cudaFuncAttributeMaxDynamicSharedMemorySize, SCORES_SMEM);

    dim3 gProj(D / 128, L / 128);
    gemm_kernel<0><<<gProj, 256>>>(query, Wq, bq, nullptr);
    gemm_kernel<1><<<gProj, 256>>>(key_, Wk, bk, nullptr);
    gemm_kernel<2><<<gProj, 256>>>(value, Wv, bv, nullptr);

    scores_stats_kernel<<<dim3(L / 128, H), 256, SCORES_SMEM>>>(mask, attn);
    attnv_kernel<<<dim3(L / 256, H), 256>>>(attn);

    gemm_kernel<3><<<gProj, 256>>>(nullptr, Wo, bo, out);
}